// round 5
// baseline (speedup 1.0000x reference)
#include <cuda_runtime.h>
#include <math.h>
#include <cstdint>

#define B_   16
#define N_   1024
#define E_   768
#define H_   12
#define D_   64
#define TOK  (B_ * N_)

// Scratch (no allocations allowed).
// Q,K: [b*H+h][n][d] with d interleaved within 8-groups (pos = 2*(k&3)+((k&7)>>2)),
//      Q pre-scaled by 0.125. V: normal layout. AO: [b][n][e], e interleaved.
__device__ float g_Q [(size_t)B_ * H_ * N_ * D_];
__device__ float g_K [(size_t)B_ * H_ * N_ * D_];
__device__ float g_V [(size_t)B_ * H_ * N_ * D_];
__device__ float g_AO[(size_t)TOK * E_];
__device__ float g_Xr[(size_t)TOK * E_];            // tf32-rounded + interleaved x
__device__ float g_Wr[4][(size_t)E_ * E_];          // tf32-rounded + interleaved W

// ---------------------------------------------------------------------------
// helpers
// ---------------------------------------------------------------------------
__device__ __forceinline__ uint32_t smem_u32(const void* p) {
    uint32_t a;
    asm("{ .reg .u64 t; cvta.to.shared.u64 t, %1; cvt.u32.u64 %0, t; }" : "=r"(a) : "l"(p));
    return a;
}
__device__ __forceinline__ uint32_t tf32b(float x) {
    uint32_t u;
    asm("cvt.rna.tf32.f32 %0, %1;" : "=r"(u) : "f"(x));
    return u;
}
__device__ __forceinline__ float u2f(uint32_t u) { return __uint_as_float(u); }
__device__ __forceinline__ uint32_t f2u(float f) { return __float_as_uint(f); }

__device__ __forceinline__ void mma8(float* c, const uint32_t* a,
                                     uint32_t b0, uint32_t b1) {
    asm volatile(
        "mma.sync.aligned.m16n8k8.row.col.f32.tf32.tf32.f32 "
        "{%0,%1,%2,%3}, {%4,%5,%6,%7}, {%8,%9}, {%0,%1,%2,%3};\n"
        : "+f"(c[0]), "+f"(c[1]), "+f"(c[2]), "+f"(c[3])
        : "r"(a[0]), "r"(a[1]), "r"(a[2]), "r"(a[3]), "r"(b0), "r"(b1));
}

#define CP16(dst, src) \
    asm volatile("cp.async.cg.shared.global [%0], [%1], 16;" :: "r"(dst), "l"(src))
#define CP_COMMIT() asm volatile("cp.async.commit_group;" ::: "memory")
template <int N>
__device__ __forceinline__ void cp_wait() {
    asm volatile("cp.async.wait_group %0;" :: "n"(N) : "memory");
}

// Fast exp on the FMA pipe (no MUFU).
__device__ __forceinline__ float fexp(float x) {
    x = fmaxf(x, -80.0f);
    float t = x * 1.4426950408889634f;
    float z = t + 12582912.0f;
    int   e = __float_as_int(z);
    float f = t - (z - 12582912.0f);
    float p = 1.3333558e-3f;
    p = fmaf(p, f, 9.6181291e-3f);
    p = fmaf(p, f, 5.5504109e-2f);
    p = fmaf(p, f, 2.4022651e-1f);
    p = fmaf(p, f, 6.9314718e-1f);
    p = fmaf(p, f, 1.0f);
    return __int_as_float(__float_as_int(p) + (e << 23));
}

// ---------------------------------------------------------------------------
// Prepass: tf32 RN round + interleave k within 8-groups.
// 8-group logical k0..k7 -> positions {0,2,4,6,1,3,5,7}.
// ---------------------------------------------------------------------------
__global__ __launch_bounds__(256) void prep8_kernel(
    const float4* __restrict__ in, float4* __restrict__ out, int n8)
{
    int i = blockIdx.x * blockDim.x + threadIdx.x;
    if (i >= n8) return;
    float4 a = in[2 * i], b = in[2 * i + 1];
    float4 o1 = make_float4(u2f(tf32b(a.x)), u2f(tf32b(b.x)),
                            u2f(tf32b(a.y)), u2f(tf32b(b.y)));
    float4 o2 = make_float4(u2f(tf32b(a.z)), u2f(tf32b(b.z)),
                            u2f(tf32b(a.w)), u2f(tf32b(b.w)));
    out[2 * i] = o1; out[2 * i + 1] = o2;
}

// ---------------------------------------------------------------------------
// tf32 mma.sync GEMM, cp.async 3-stage, XOR-swizzled smem, 64x64 warp tiles.
// Block 128 threads (4 warps, 2x2), tile 128x128x32.
// Operands pre-interleaved -> all fragment loads LDS.64.
// QKV=true: grid.y=18, which=by/6: 0=Q (perm + x0.125), 1=K (perm), 2=V (plain).
// ---------------------------------------------------------------------------
#define GSTG 8192                            // floats/stage: A 128*32 + B 128*32
#define GEMM_SMEM (3 * GSTG * 4)             // 98304 B

template <bool QKV>
__global__ __launch_bounds__(128, 2) void tf32_gemm(
    const float* __restrict__ A, const float* __restrict__ Wbase,
    const float* __restrict__ bp0, const float* __restrict__ bp1,
    const float* __restrict__ bp2,
    float* __restrict__ C0, float* __restrict__ C1, float* __restrict__ C2)
{
    extern __shared__ float sm[];
    const uint32_t sb = smem_u32(sm);
    const int tid = threadIdx.x;
    const int wid = tid >> 5, lane = tid & 31;
    const int g = lane >> 2, q = lane & 3;
    const int wm = wid >> 1, wn = wid & 1;
    const int m0 = blockIdx.x * 128;

    int n0, which = 0;
    const float* W;
    const float* bias;
    float* C;
    if (QKV) {
        which = blockIdx.y / 6;
        n0 = (blockIdx.y % 6) * 128;
        W = Wbase + (size_t)which * E_ * E_;
        bias = (which == 0) ? bp0 : (which == 1) ? bp1 : bp2;
        C = (which == 0) ? C0 : (which == 1) ? C1 : C2;
    } else {
        n0 = blockIdx.y * 128;
        W = Wbase; bias = bp0; C = C0;
    }

    auto issue = [&](int ko) {
        uint32_t base = sb + (uint32_t)(ko % 3) * GSTG * 4;
        const float* Ab = A + (size_t)m0 * E_ + ko * 32;
        const float* Wb = W + (size_t)n0 * E_ + ko * 32;
#pragma unroll
        for (int i = 0; i < 8; i++) {
            int c = tid + i * 128;              // 0..1023
            int row = c >> 3, c4 = c & 7;
            uint32_t off = (uint32_t)(row * 32 + ((c4 ^ (row & 7)) * 4)) * 4;
            CP16(base + off, Ab + (size_t)row * E_ + c4 * 4);
            CP16(base + 4096 * 4 + off, Wb + (size_t)row * E_ + c4 * 4);
        }
    };

    float acc[4][8][4];
#pragma unroll
    for (int mi = 0; mi < 4; mi++)
#pragma unroll
        for (int ni = 0; ni < 8; ni++)
#pragma unroll
            for (int r = 0; r < 4; r++) acc[mi][ni][r] = 0.0f;

    issue(0); CP_COMMIT();
    issue(1); CP_COMMIT();

    for (int ko = 0; ko < E_ / 32; ko++) {
        if (ko + 2 < E_ / 32) issue(ko + 2);
        CP_COMMIT();
        cp_wait<2>();
        __syncthreads();
        const float* pa = sm + (ko % 3) * GSTG;
        const float* pb = pa + 4096;
#pragma unroll
        for (int kc = 0; kc < 4; kc++) {
            const int ch = ((kc * 2 + (q >> 1)) ^ g) * 4 + (q & 1) * 2;
            uint32_t af[4][4];
#pragma unroll
            for (int mi = 0; mi < 4; mi++) {
                const float* p0 = pa + (wm * 64 + mi * 16 + g) * 32 + ch;
                float2 lo = *(const float2*)p0;
                float2 hi = *(const float2*)(p0 + 8 * 32);
                af[mi][0] = f2u(lo.x); af[mi][1] = f2u(hi.x);
                af[mi][2] = f2u(lo.y); af[mi][3] = f2u(hi.y);
            }
#pragma unroll
            for (int ni = 0; ni < 8; ni++) {
                float2 bv = *(const float2*)(pb + (wn * 64 + ni * 8 + g) * 32 + ch);
                uint32_t b0 = f2u(bv.x), b1 = f2u(bv.y);
#pragma unroll
                for (int mi = 0; mi < 4; mi++) mma8(acc[mi][ni], af[mi], b0, b1);
            }
        }
        __syncthreads();
    }

    // epilogue
    const int p0i = (q < 2) ? 4 * q : 4 * q - 7;   // interleaved pos of k=2q
#pragma unroll
    for (int mi = 0; mi < 4; mi++) {
        int r0 = m0 + wm * 64 + mi * 16 + g, r1 = r0 + 8;
#pragma unroll
        for (int ni = 0; ni < 8; ni++) {
            int cb = n0 + wn * 64 + ni * 8;
            int c0 = cb + 2 * q;
            float bx = __ldg(bias + c0), by = __ldg(bias + c0 + 1);
            float v00 = acc[mi][ni][0] + bx, v01 = acc[mi][ni][1] + by;
            float v10 = acc[mi][ni][2] + bx, v11 = acc[mi][ni][3] + by;
            if (QKV) {
                if (which == 0) { v00 *= 0.125f; v01 *= 0.125f; v10 *= 0.125f; v11 *= 0.125f; }
                v00 = u2f(tf32b(v00)); v01 = u2f(tf32b(v01));
                v10 = u2f(tf32b(v10)); v11 = u2f(tf32b(v11));
                int h = cb >> 6;
                int bb0 = r0 >> 10, nn0 = r0 & (N_ - 1);
                int bb1 = r1 >> 10, nn1 = r1 & (N_ - 1);
                float* d0 = C + (((size_t)bb0 * H_ + h) * N_ + nn0) * D_ + (cb & 63);
                float* d1 = C + (((size_t)bb1 * H_ + h) * N_ + nn1) * D_ + (cb & 63);
                if (which < 2) {  // Q,K: d-interleaved
                    d0[p0i] = v00; d0[p0i + 2] = v01;
                    d1[p0i] = v10; d1[p0i + 2] = v11;
                } else {          // V: plain
                    *(float2*)(d0 + 2 * q) = make_float2(v00, v01);
                    *(float2*)(d1 + 2 * q) = make_float2(v10, v11);
                }
            } else {
                *(float2*)(C + (size_t)r0 * E_ + c0) = make_float2(v00, v01);
                *(float2*)(C + (size_t)r1 * E_ + c0) = make_float2(v10, v11);
            }
        }
    }
}

// ---------------------------------------------------------------------------
// Flash attention. Q/K interleaved in gmem (Q pre-scaled); V transposed
// in-kernel to VsT (rows=d, cols=key-interleaved). All frag loads LDS.64.
// smem (floats): Qs[128*64] @0, Ks 2x[64*64] @8192, VsT[64*64] @16384.
// 8 warps; warp = 16 q-rows x 64 keys. XOR swizzle: chunk16 ^ (row&7).
// ---------------------------------------------------------------------------
#define ATTN_SMEM (20480 * 4)   // 81920 B

__global__ __launch_bounds__(256, 2) void attn_mma(
    const float* __restrict__ Q, const float* __restrict__ K,
    const float* __restrict__ V, float* __restrict__ O)
{
    extern __shared__ float sm[];
    const uint32_t sb = smem_u32(sm);
    const int tid = threadIdx.x;
    const int wid = tid >> 5, lane = tid & 31;
    const int g = lane >> 2, q = lane & 3;
    const int bh = blockIdx.y;
    const int q0 = blockIdx.x * 128;

    const float* Qb = Q + (size_t)bh * N_ * D_;
    const float* Kb = K + (size_t)bh * N_ * D_;
    const float* Vb = V + (size_t)bh * N_ * D_;

    // Q -> smem (cp.async, swizzled)
#pragma unroll
    for (int i = 0; i < 8; i++) {
        int c = tid + i * 256;              // 2048 16B chunks
        int row = c >> 4, c4 = c & 15;
        CP16(sb + (uint32_t)(row * 64 + (c4 ^ (row & 7)) * 4) * 4,
             Qb + (size_t)(q0 + row) * D_ + c4 * 4);
    }
    CP_COMMIT();

    auto issueK = [&](int ck) {
        uint32_t kb = sb + (uint32_t)(8192 + (ck & 1) * 4096) * 4;
        const float* Kc = Kb + (size_t)ck * 64 * D_;
#pragma unroll
        for (int i = 0; i < 4; i++) {
            int c = tid + i * 256;          // 1024 chunks
            int row = c >> 4, c4 = c & 15;
            CP16(kb + (uint32_t)(row * 64 + (c4 ^ (row & 7)) * 4) * 4,
                 Kc + (size_t)row * D_ + c4 * 4);
        }
    };
    issueK(0); CP_COMMIT();

    // V prefetch (registers)
    const int vkey = tid & 63, vdg = tid >> 6;
    const int vkp = (vkey & ~7) + 2 * (vkey & 3) + ((vkey & 7) >> 2);
    float4 vr[4];
#pragma unroll
    for (int i = 0; i < 4; i++)
        vr[i] = *(const float4*)(Vb + (size_t)vkey * D_ + (vdg + i * 4) * 4);

    cp_wait<1>();   // Q done (K0 may still be in flight)
    __syncthreads();

    float of[8][4];
#pragma unroll
    for (int ni = 0; ni < 8; ni++)
#pragma unroll
        for (int r = 0; r < 4; r++) of[ni][r] = 0.0f;
    float mA = -INFINITY, mB = -INFINITY, lA = 0.0f, lB = 0.0f;

    const int chq = (q >> 1), wq = (q & 1) * 2;

    for (int ck = 0; ck < N_ / 64; ck++) {
        if (ck + 1 < N_ / 64) issueK(ck + 1);
        CP_COMMIT();
        cp_wait<1>();
        __syncthreads();   // K(ck) visible; all prev PV reads of VsT done
        const float* Ksp = sm + 8192 + (ck & 1) * 4096;

        // S = (Q/8) K^T
        float sf[8][4];
#pragma unroll
        for (int ni = 0; ni < 8; ni++)
#pragma unroll
            for (int r = 0; r < 4; r++) sf[ni][r] = 0.0f;
#pragma unroll
        for (int kc = 0; kc < 8; kc++) {
            const int ch = ((kc * 2 + chq) ^ g) * 4 + wq;
            uint32_t qf[4];
            {
                const float* p0 = sm + (wid * 16 + g) * 64 + ch;
                float2 lo = *(const float2*)p0;
                float2 hi = *(const float2*)(p0 + 8 * 64);
                qf[0] = f2u(lo.x); qf[1] = f2u(hi.x);
                qf[2] = f2u(lo.y); qf[3] = f2u(hi.y);
            }
#pragma unroll
            for (int ni = 0; ni < 8; ni++) {
                float2 bv = *(const float2*)(Ksp + (ni * 8 + g) * 64 + ch);
                mma8(sf[ni], qf, f2u(bv.x), f2u(bv.y));
            }
        }

        // Online softmax
        float mxA = -INFINITY, mxB = -INFINITY;
#pragma unroll
        for (int ni = 0; ni < 8; ni++) {
            mxA = fmaxf(mxA, fmaxf(sf[ni][0], sf[ni][1]));
            mxB = fmaxf(mxB, fmaxf(sf[ni][2], sf[ni][3]));
        }
        mxA = fmaxf(mxA, __shfl_xor_sync(0xffffffffu, mxA, 1));
        mxA = fmaxf(mxA, __shfl_xor_sync(0xffffffffu, mxA, 2));
        mxB = fmaxf(mxB, __shfl_xor_sync(0xffffffffu, mxB, 1));
        mxB = fmaxf(mxB, __shfl_xor_sync(0xffffffffu, mxB, 2));
        float nmA = fmaxf(mA, mxA), nmB = fmaxf(mB, mxB);
        float cA = fexp(mA - nmA), cB = fexp(mB - nmB);
        float suA = 0.0f, suB = 0.0f;
#pragma unroll
        for (int ni = 0; ni < 8; ni++) {
            sf[ni][0] = fexp(sf[ni][0] - nmA);
            sf[ni][1] = fexp(sf[ni][1] - nmA);
            sf[ni][2] = fexp(sf[ni][2] - nmB);
            sf[ni][3] = fexp(sf[ni][3] - nmB);
            suA += sf[ni][0] + sf[ni][1];
            suB += sf[ni][2] + sf[ni][3];
        }
        suA += __shfl_xor_sync(0xffffffffu, suA, 1);
        suA += __shfl_xor_sync(0xffffffffu, suA, 2);
        suB += __shfl_xor_sync(0xffffffffu, suB, 1);
        suB += __shfl_xor_sync(0xffffffffu, suB, 2);
        lA = lA * cA + suA; lB = lB * cB + suB;
        mA = nmA; mB = nmB;
#pragma unroll
        for (int ni = 0; ni < 8; ni++) {
            of[ni][0] *= cA; of[ni][1] *= cA;
            of[ni][2] *= cB; of[ni][3] *= cB;
        }

        // Store V^T (rows=d, cols=key-interleaved, swizzled)
#pragma unroll
        for (int i = 0; i < 4; i++) {
            float vv[4] = {vr[i].x, vr[i].y, vr[i].z, vr[i].w};
#pragma unroll
            for (int c = 0; c < 4; c++) {
                int d = (vdg + i * 4) * 4 + c;
                sm[16384 + d * 64 + (((vkp >> 2) ^ (d & 7)) * 4) + (vkp & 3)] = vv[c];
            }
        }
        if (ck + 1 < N_ / 64) {
            const float* Vn = Vb + (size_t)(ck + 1) * 64 * D_;
#pragma unroll
            for (int i = 0; i < 4; i++)
                vr[i] = *(const float4*)(Vn + (size_t)vkey * D_ + (vdg + i * 4) * 4);
        }
        __syncthreads();

        // O += P @ V : shuffle-transpose sf -> A fragment, V^T from smem
        const int srcl = (lane & 28) | (q >> 1);
        const bool odd = (q & 1);
#pragma unroll
        for (int kc = 0; kc < 8; kc++) {
            float e0 = __shfl_sync(0xffffffffu, sf[kc][0], srcl);
            float o0 = __shfl_sync(0xffffffffu, sf[kc][1], srcl);
            float e1 = __shfl_sync(0xffffffffu, sf[kc][2], srcl);
            float o1 = __shfl_sync(0xffffffffu, sf[kc][3], srcl);
            float e2 = __shfl_sync(0xffffffffu, sf[kc][0], srcl + 2);
            float o2 = __shfl_sync(0xffffffffu, sf[kc][1], srcl + 2);
            float e3 = __shfl_sync(0xffffffffu, sf[kc][2], srcl + 2);
            float o3 = __shfl_sync(0xffffffffu, sf[kc][3], srcl + 2);
            uint32_t a[4];
            a[0] = tf32b(odd ? o0 : e0);
            a[1] = tf32b(odd ? o1 : e1);
            a[2] = tf32b(odd ? o2 : e2);
            a[3] = tf32b(odd ? o3 : e3);
            const int ch = ((kc * 2 + chq) ^ g) * 4 + wq;
#pragma unroll
            for (int ni = 0; ni < 8; ni++) {
                float2 bv = *(const float2*)(sm + 16384 + (ni * 8 + g) * 64 + ch);
                mma8(of[ni], a, f2u(bv.x), f2u(bv.y));
            }
        }
    }

    // Epilogue -> AO [b, n, E], tf32-rounded + e-interleaved (for out-proj)
    const int bb = bh / H_, hh = bh - bb * H_;
    const int p0i = (q < 2) ? 4 * q : 4 * q - 7;
    float iA = 1.0f / lA, iB = 1.0f / lB;
    int rA = q0 + wid * 16 + g, rB = rA + 8;
#pragma unroll
    for (int ni = 0; ni < 8; ni++) {
        float* dA = O + ((size_t)(bb * N_ + rA)) * E_ + hh * D_ + ni * 8;
        float* dB = O + ((size_t)(bb * N_ + rB)) * E_ + hh * D_ + ni * 8;
        dA[p0i]     = u2f(tf32b(of[ni][0] * iA));
        dA[p0i + 2] = u2f(tf32b(of[ni][1] * iA));
        dB[p0i]     = u2f(tf32b(of[ni][2] * iB));
        dB[p0i + 2] = u2f(tf32b(of[ni][3] * iB));
    }
}

// ---------------------------------------------------------------------------
extern "C" void kernel_launch(void* const* d_in, const int* in_sizes, int n_in,
                              void* d_out, int out_size)
{
    const float* x  = (const float*)d_in[0];
    const float* Wq = (const float*)d_in[1];
    const float* bq = (const float*)d_in[2];
    const float* Wk = (const float*)d_in[3];
    const float* bk = (const float*)d_in[4];
    const float* Wv = (const float*)d_in[5];
    const float* bv = (const float*)d_in[6];
    const float* Wo = (const float*)d_in[7];
    const float* bo = (const float*)d_in[8];
    float* out = (float*)d_out;

    float *Qp, *Kp, *Vp, *AOp, *Xr, *Wr;
    cudaGetSymbolAddress((void**)&Qp,  g_Q);
    cudaGetSymbolAddress((void**)&Kp,  g_K);
    cudaGetSymbolAddress((void**)&Vp,  g_V);
    cudaGetSymbolAddress((void**)&AOp, g_AO);
    cudaGetSymbolAddress((void**)&Xr,  g_Xr);
    cudaGetSymbolAddress((void**)&Wr,  g_Wr);

    cudaFuncSetAttribute(tf32_gemm<true>,
                         cudaFuncAttributeMaxDynamicSharedMemorySize, GEMM_SMEM);
    cudaFuncSetAttribute(tf32_gemm<false>,
                         cudaFuncAttributeMaxDynamicSharedMemorySize, GEMM_SMEM);
    cudaFuncSetAttribute(attn_mma,
                         cudaFuncAttributeMaxDynamicSharedMemorySize, ATTN_SMEM);

    // Prepass: round + interleave
    {
        int n8x = TOK * E_ / 8, n8w = E_ * E_ / 8;
        prep8_kernel<<<(n8x + 255) / 256, 256>>>((const float4*)x, (float4*)Xr, n8x);
        prep8_kernel<<<(n8w + 255) / 256, 256>>>((const float4*)Wq, (float4*)(Wr + 0 * (size_t)E_ * E_), n8w);
        prep8_kernel<<<(n8w + 255) / 256, 256>>>((const float4*)Wk, (float4*)(Wr + 1 * (size_t)E_ * E_), n8w);
        prep8_kernel<<<(n8w + 255) / 256, 256>>>((const float4*)Wv, (float4*)(Wr + 2 * (size_t)E_ * E_), n8w);
        prep8_kernel<<<(n8w + 255) / 256, 256>>>((const float4*)Wo, (float4*)(Wr + 3 * (size_t)E_ * E_), n8w);
    }

    // Fused QKV projection
    dim3 gqkv(TOK / 128, 18);
    tf32_gemm<true><<<gqkv, 128, GEMM_SMEM>>>(Xr, Wr, bq, bk, bv, Qp, Kp, Vp);

    // Attention
    dim3 ga(N_ / 128, B_ * H_);
    attn_mma<<<ga, 256, ATTN_SMEM>>>(Qp, Kp, Vp, AOp);

    // Output projection
    dim3 go(TOK / 128, E_ / 128);
    tf32_gemm<false><<<go, 128, GEMM_SMEM>>>(
        AOp, Wr + 3 * (size_t)E_ * E_, bo, bo, bo, out, out, out);
}